// round 1
// baseline (speedup 1.0000x reference)
#include <cuda_runtime.h>

#define BB 32
#define PP 1024
#define HH 8
#define DD 64
#define HIDN 512
#define MMEM 64
#define RR 64

// Scratch (allocation-free: device globals)
__device__ float g_A[HH * MMEM];
__device__ float g_s1[BB * HH];
__device__ float g_s2[BB * HH];
__device__ float g_WUv[HH * RR];
__device__ float g_WUb[HH * RR];
__device__ float g_WVv[HH * RR];
__device__ float g_WVb[HH * RR];
__device__ float g_Ut[BB * RR * PP];  // [b][r][p]  (transposed!)
__device__ float g_Vt[BB * RR * PP];  // [b][r][p]

// ---------------------------------------------------------------------------
// Stage 0: tiny precomputes.
//  A[h,m]      = sum_d w_k[h*64+d] * w_mem[m*64+d]       (bias b_k cancels in softmax)
//  WUv[h,r]    = sum_d w_u [r,h*64+d] * w_v[h*64+d]
//  WUb[h,r]    = sum_d w_u [r,h*64+d] * b_v[h*64+d]
//  WVv[h,r]    = sum_d w_v2[r,h*64+d] * w_v[h*64+d]
//  WVb[h,r]    = sum_d w_v2[r,h*64+d] * b_v[h*64+d]
// ---------------------------------------------------------------------------
__global__ void precompute_kernel(const float* __restrict__ w_k,
                                  const float* __restrict__ w_mem,
                                  const float* __restrict__ w_u,
                                  const float* __restrict__ w_v,
                                  const float* __restrict__ b_v,
                                  const float* __restrict__ w_v2) {
    int which = blockIdx.x;
    int t = threadIdx.x;  // 0..511
    if (which == 0) {
        int h = t >> 6, m = t & 63;
        float s = 0.f;
#pragma unroll
        for (int d = 0; d < DD; d++) s += w_k[h * DD + d] * w_mem[m * DD + d];
        g_A[h * MMEM + m] = s;
    } else {
        int h = t >> 6, r = t & 63;
        const float* wsrc = (which <= 2) ? w_u : w_v2;
        const float* vec = (which & 1) ? w_v : b_v;
        float s = 0.f;
#pragma unroll
        for (int d = 0; d < DD; d++) s += wsrc[r * HIDN + h * DD + d] * vec[h * DD + d];
        if (which == 1) g_WUv[h * RR + r] = s;
        else if (which == 2) g_WUb[h * RR + r] = s;
        else if (which == 3) g_WVv[h * RR + r] = s;
        else g_WVb[h * RR + r] = s;
    }
}

// ---------------------------------------------------------------------------
// Stage 1: per (b,h):  t[m] = (sum_p e^{a*x_p - shift} * x_p) / (sum_p e^{...})
//          then s1 = sum_m t, s2 = sum_m t^2.   One block per (b,h).
// ---------------------------------------------------------------------------
__global__ void stage1_kernel(const float* __restrict__ x) {
    __shared__ float xs[PP];
    __shared__ float red[16];
    __shared__ float ts[MMEM];
    __shared__ float smm[2];
    int b = blockIdx.x >> 3;
    int h = blockIdx.x & 7;
    int tid = threadIdx.x;  // 256 threads
    float mx = -1e30f, mn = 1e30f;
    for (int i = tid; i < PP; i += 256) {
        float v = x[b * PP + i];
        xs[i] = v;
        mx = fmaxf(mx, v);
        mn = fminf(mn, v);
    }
#pragma unroll
    for (int o = 16; o; o >>= 1) {
        mx = fmaxf(mx, __shfl_xor_sync(0xffffffffu, mx, o));
        mn = fminf(mn, __shfl_xor_sync(0xffffffffu, mn, o));
    }
    int warp = tid >> 5, lane = tid & 31;
    if (lane == 0) { red[warp] = mx; red[8 + warp] = mn; }
    __syncthreads();
    if (tid == 0) {
        float a = red[0], c = red[8];
#pragma unroll
        for (int w = 1; w < 8; w++) { a = fmaxf(a, red[w]); c = fminf(c, red[8 + w]); }
        smm[0] = a; smm[1] = c;
    }
    __syncthreads();
    float bmax = smm[0], bmin = smm[1];
#pragma unroll
    for (int mi = 0; mi < 8; mi++) {
        int m = warp * 8 + mi;
        float a = g_A[h * MMEM + m];
        float shift = (a > 0.f) ? a * bmax : a * bmin;
        float Z = 0.f, Zx = 0.f;
        for (int p = lane; p < PP; p += 32) {
            float xv = xs[p];
            float e = __expf(fmaf(a, xv, -shift));
            Z += e;
            Zx = fmaf(e, xv, Zx);
        }
#pragma unroll
        for (int o = 16; o; o >>= 1) {
            Z += __shfl_xor_sync(0xffffffffu, Z, o);
            Zx += __shfl_xor_sync(0xffffffffu, Zx, o);
        }
        if (lane == 0) ts[m] = Zx / Z;
    }
    __syncthreads();
    if (tid < 32) {
        float t0 = ts[tid], t1 = ts[tid + 32];
        float s1 = t0 + t1, s2 = t0 * t0 + t1 * t1;
#pragma unroll
        for (int o = 16; o; o >>= 1) {
            s1 += __shfl_xor_sync(0xffffffffu, s1, o);
            s2 += __shfl_xor_sync(0xffffffffu, s2, o);
        }
        if (tid == 0) { g_s1[blockIdx.x] = s1; g_s2[blockIdx.x] = s2; }
    }
}

// ---------------------------------------------------------------------------
// Stage 2: one warp per (b,p).
//   per head h:  qv = sum_d phi(x*wq+bq)*wv,  qb = sum_d phi(...)*bv
//   alpha = qv*s2 + qb*s1 ; beta = qv*s1 + 64*qb
//   U[r] = b_u[r] + sum_h alpha*WUv[h,r] + beta*WUb[h,r]   (same for V)
// Output written TRANSPOSED: g_Ut[b][r][p], coalesced via smem tile.
// Block = 1024 threads = 32 warps = 32 consecutive p of same batch.
// ---------------------------------------------------------------------------
__global__ void stage2_kernel(const float* __restrict__ x,
                              const float* __restrict__ w_q,
                              const float* __restrict__ b_q,
                              const float* __restrict__ w_v,
                              const float* __restrict__ b_v,
                              const float* __restrict__ b_u,
                              const float* __restrict__ b_v2) {
    __shared__ float su[RR][33];
    __shared__ float sv[RR][33];
    int tid = threadIdx.x;
    int warp = tid >> 5, lane = tid & 31;
    int g = blockIdx.x * 32 + warp;
    int b = g >> 10;
    int p = g & 1023;
    float xv = x[b * PP + p];
    float u0 = 0.f, u1 = 0.f, v0 = 0.f, v1 = 0.f;
#pragma unroll
    for (int h = 0; h < HH; h++) {
        int base = h * DD;
        float a0 = fmaf(xv, w_q[base + lane], b_q[base + lane]);
        float a1 = fmaf(xv, w_q[base + 32 + lane], b_q[base + 32 + lane]);
        float phi0 = (a0 > 0.f) ? (a0 + 1.f) : __expf(a0);
        float phi1 = (a1 > 0.f) ? (a1 + 1.f) : __expf(a1);
        float qv = phi0 * w_v[base + lane] + phi1 * w_v[base + 32 + lane];
        float qb = phi0 * b_v[base + lane] + phi1 * b_v[base + 32 + lane];
#pragma unroll
        for (int o = 16; o; o >>= 1) {
            qv += __shfl_xor_sync(0xffffffffu, qv, o);
            qb += __shfl_xor_sync(0xffffffffu, qb, o);
        }
        float s1v = g_s1[b * HH + h], s2v = g_s2[b * HH + h];
        float al = qv * s2v + qb * s1v;
        float be = qv * s1v + qb * (float)MMEM;
        u0 += al * g_WUv[base + lane] + be * g_WUb[base + lane];
        u1 += al * g_WUv[base + 32 + lane] + be * g_WUb[base + 32 + lane];
        v0 += al * g_WVv[base + lane] + be * g_WVb[base + lane];
        v1 += al * g_WVv[base + 32 + lane] + be * g_WVb[base + 32 + lane];
    }
    su[lane][warp] = u0 + b_u[lane];
    su[lane + 32][warp] = u1 + b_u[lane + 32];
    sv[lane][warp] = v0 + b_v2[lane];
    sv[lane + 32][warp] = v1 + b_v2[lane + 32];
    __syncthreads();
    int p0 = (blockIdx.x * 32) & 1023;
#pragma unroll
    for (int idx = tid; idx < RR * 32; idx += 1024) {
        int r = idx >> 5, pi = idx & 31;
        g_Ut[(b * RR + r) * PP + p0 + pi] = su[r][pi];
        g_Vt[(b * RR + r) * PP + p0 + pi] = sv[r][pi];
    }
}

// ---------------------------------------------------------------------------
// Stage 3: C[b] = Ut[b]^T @ Vt[b]   (k-major operands, no smem transpose).
// 128x128 block tile, K=64 in two 32-chunks, 8x8 per thread, fp32 FFMA.
// ---------------------------------------------------------------------------
__global__ void __launch_bounds__(256, 2) gemm_kernel(float* __restrict__ C) {
    __shared__ float As[32][128];
    __shared__ float Bs[32][128];
    int b = blockIdx.z;
    int m0 = blockIdx.y * 128, n0 = blockIdx.x * 128;
    const float* Ag = g_Ut + b * RR * PP;
    const float* Bg = g_Vt + b * RR * PP;
    float* Cb = C + (size_t)b * PP * PP;
    int tid = threadIdx.x;
    int tx = tid & 15, ty = tid >> 4;
    float acc[8][8];
#pragma unroll
    for (int i = 0; i < 8; i++)
#pragma unroll
        for (int j = 0; j < 8; j++) acc[i][j] = 0.f;

    for (int kk = 0; kk < RR; kk += 32) {
#pragma unroll
        for (int i = 0; i < 4; i++) {
            int f = tid + i * 256;
            int k = f >> 5, mq = (f & 31) << 2;
            *(float4*)&As[k][mq] = *(const float4*)&Ag[(kk + k) * PP + m0 + mq];
            *(float4*)&Bs[k][mq] = *(const float4*)&Bg[(kk + k) * PP + n0 + mq];
        }
        __syncthreads();
#pragma unroll
        for (int k = 0; k < 32; k++) {
            float4 fa0 = *(float4*)&As[k][ty * 8];
            float4 fa1 = *(float4*)&As[k][ty * 8 + 4];
            float4 fb0 = *(float4*)&Bs[k][tx * 8];
            float4 fb1 = *(float4*)&Bs[k][tx * 8 + 4];
            float av[8] = {fa0.x, fa0.y, fa0.z, fa0.w, fa1.x, fa1.y, fa1.z, fa1.w};
            float bv[8] = {fb0.x, fb0.y, fb0.z, fb0.w, fb1.x, fb1.y, fb1.z, fb1.w};
#pragma unroll
            for (int i = 0; i < 8; i++)
#pragma unroll
                for (int j = 0; j < 8; j++) acc[i][j] = fmaf(av[i], bv[j], acc[i][j]);
        }
        __syncthreads();
    }
#pragma unroll
    for (int i = 0; i < 8; i++) {
        size_t row = (size_t)(m0 + ty * 8 + i) * PP;
        float4 o0 = make_float4(acc[i][0], acc[i][1], acc[i][2], acc[i][3]);
        float4 o1 = make_float4(acc[i][4], acc[i][5], acc[i][6], acc[i][7]);
        *(float4*)&Cb[row + n0 + tx * 8] = o0;
        *(float4*)&Cb[row + n0 + tx * 8 + 4] = o1;
    }
}

extern "C" void kernel_launch(void* const* d_in, const int* in_sizes, int n_in,
                              void* d_out, int out_size) {
    const float* x    = (const float*)d_in[0];
    const float* w_q  = (const float*)d_in[1];
    const float* b_q  = (const float*)d_in[2];
    const float* w_k  = (const float*)d_in[3];
    // d_in[4] = b_k: mathematically cancels in the softmax over p — unused.
    const float* w_v  = (const float*)d_in[5];
    const float* b_v  = (const float*)d_in[6];
    const float* w_mem = (const float*)d_in[7];
    const float* w_u  = (const float*)d_in[8];
    const float* b_u  = (const float*)d_in[9];
    const float* w_v2 = (const float*)d_in[10];
    const float* b_v2 = (const float*)d_in[11];
    float* out = (float*)d_out;

    precompute_kernel<<<5, 512>>>(w_k, w_mem, w_u, w_v, b_v, w_v2);
    stage1_kernel<<<BB * HH, 256>>>(x);
    stage2_kernel<<<(BB * PP) / 32, 1024>>>(x, w_q, b_q, w_v, b_v, b_u, b_v2);
    gemm_kernel<<<dim3(PP / 128, PP / 128, BB), 256>>>(out);
}

// round 3
// speedup vs baseline: 1.4669x; 1.4669x over previous
#include <cuda_runtime.h>
#include <cuda_bf16.h>
#include <cstdint>

#define BB 32
#define PP 1024
#define HH 8
#define DD 64
#define HIDN 512
#define MMEM 64
#define RR 64

// ------------------------- device scratch (no allocs) -----------------------
__device__ float g_A[HH * MMEM];
__device__ float g_s1[BB * HH];
__device__ float g_s2[BB * HH];
__device__ float g_WUv[HH * RR];
__device__ float g_WUb[HH * RR];
__device__ float g_WVv[HH * RR];
__device__ float g_WVb[HH * RR];
// bf16 split operands, layout [b][p][r] (K-major rows of 64 bf16 = 128B)
__device__ __nv_bfloat16 g_Uh[BB * PP * RR];
__device__ __nv_bfloat16 g_Ul[BB * PP * RR];
__device__ __nv_bfloat16 g_Vh[BB * PP * RR];
__device__ __nv_bfloat16 g_Vl[BB * PP * RR];

// ---------------------------------------------------------------------------
// Stage 0: tiny precomputes (b_k cancels in the softmax over p).
// ---------------------------------------------------------------------------
__global__ void precompute_kernel(const float* __restrict__ w_k,
                                  const float* __restrict__ w_mem,
                                  const float* __restrict__ w_u,
                                  const float* __restrict__ w_v,
                                  const float* __restrict__ b_v,
                                  const float* __restrict__ w_v2) {
    int which = blockIdx.x;
    int t = threadIdx.x;  // 0..511
    if (which == 0) {
        int h = t >> 6, m = t & 63;
        float s = 0.f;
#pragma unroll
        for (int d = 0; d < DD; d++) s += w_k[h * DD + d] * w_mem[m * DD + d];
        g_A[h * MMEM + m] = s;
    } else {
        int h = t >> 6, r = t & 63;
        const float* wsrc = (which <= 2) ? w_u : w_v2;
        const float* vec = (which & 1) ? w_v : b_v;
        float s = 0.f;
#pragma unroll
        for (int d = 0; d < DD; d++) s += wsrc[r * HIDN + h * DD + d] * vec[h * DD + d];
        if (which == 1) g_WUv[h * RR + r] = s;
        else if (which == 2) g_WUb[h * RR + r] = s;
        else if (which == 3) g_WVv[h * RR + r] = s;
        else g_WVb[h * RR + r] = s;
    }
}

// ---------------------------------------------------------------------------
// Stage 1: per (b,h): t[m] = softmax-weighted mean of x; s1=sum t, s2=sum t^2
// ---------------------------------------------------------------------------
__global__ void stage1_kernel(const float* __restrict__ x) {
    __shared__ float xs[PP];
    __shared__ float red[16];
    __shared__ float ts[MMEM];
    __shared__ float smm[2];
    int b = blockIdx.x >> 3;
    int h = blockIdx.x & 7;
    int tid = threadIdx.x;  // 256 threads
    float mx = -1e30f, mn = 1e30f;
    for (int i = tid; i < PP; i += 256) {
        float v = x[b * PP + i];
        xs[i] = v;
        mx = fmaxf(mx, v);
        mn = fminf(mn, v);
    }
#pragma unroll
    for (int o = 16; o; o >>= 1) {
        mx = fmaxf(mx, __shfl_xor_sync(0xffffffffu, mx, o));
        mn = fminf(mn, __shfl_xor_sync(0xffffffffu, mn, o));
    }
    int warp = tid >> 5, lane = tid & 31;
    if (lane == 0) { red[warp] = mx; red[8 + warp] = mn; }
    __syncthreads();
    if (tid == 0) {
        float a = red[0], c = red[8];
#pragma unroll
        for (int w = 1; w < 8; w++) { a = fmaxf(a, red[w]); c = fminf(c, red[8 + w]); }
        smm[0] = a; smm[1] = c;
    }
    __syncthreads();
    float bmax = smm[0], bmin = smm[1];
#pragma unroll
    for (int mi = 0; mi < 8; mi++) {
        int m = warp * 8 + mi;
        float a = g_A[h * MMEM + m];
        float shift = (a > 0.f) ? a * bmax : a * bmin;
        float Z = 0.f, Zx = 0.f;
        for (int p = lane; p < PP; p += 32) {
            float xv = xs[p];
            float e = __expf(fmaf(a, xv, -shift));
            Z += e;
            Zx = fmaf(e, xv, Zx);
        }
#pragma unroll
        for (int o = 16; o; o >>= 1) {
            Z += __shfl_xor_sync(0xffffffffu, Z, o);
            Zx += __shfl_xor_sync(0xffffffffu, Zx, o);
        }
        if (lane == 0) ts[m] = Zx / Z;
    }
    __syncthreads();
    if (tid < 32) {
        float t0 = ts[tid], t1 = ts[tid + 32];
        float s1 = t0 + t1, s2 = t0 * t0 + t1 * t1;
#pragma unroll
        for (int o = 16; o; o >>= 1) {
            s1 += __shfl_xor_sync(0xffffffffu, s1, o);
            s2 += __shfl_xor_sync(0xffffffffu, s2, o);
        }
        if (tid == 0) { g_s1[blockIdx.x] = s1; g_s2[blockIdx.x] = s2; }
    }
}

// ---------------------------------------------------------------------------
// Stage 2: one warp per (b,p); all weight tables cached in smem.
// Outputs bf16 hi/lo splits of U,V rows [b][p][r].
// ---------------------------------------------------------------------------
__global__ void __launch_bounds__(1024) stage2_kernel(const float* __restrict__ x,
                                                      const float* __restrict__ w_q,
                                                      const float* __restrict__ b_q,
                                                      const float* __restrict__ w_v,
                                                      const float* __restrict__ b_v,
                                                      const float* __restrict__ b_u,
                                                      const float* __restrict__ b_v2) {
    __shared__ float swq[HIDN], sbq[HIDN], swv[HIDN], sbv[HIDN];
    __shared__ float suv[HIDN], sub[HIDN], svv[HIDN], svb[HIDN];
    __shared__ float sbu[RR], sbv2[RR], ss1[HH], ss2[HH];
    int tid = threadIdx.x;
    int warp = tid >> 5, lane = tid & 31;
    int g = blockIdx.x * 32 + warp;
    int b = g >> 10;
    int p = g & 1023;
    if (tid < HIDN) {
        swq[tid] = w_q[tid]; sbq[tid] = b_q[tid];
        swv[tid] = w_v[tid]; sbv[tid] = b_v[tid];
        suv[tid] = g_WUv[tid]; sub[tid] = g_WUb[tid];
        svv[tid] = g_WVv[tid]; svb[tid] = g_WVb[tid];
        if (tid < RR) { sbu[tid] = b_u[tid]; sbv2[tid] = b_v2[tid]; }
        if (tid < HH) { ss1[tid] = g_s1[b * HH + tid]; ss2[tid] = g_s2[b * HH + tid]; }
    }
    __syncthreads();
    float xv = x[b * PP + p];
    float u0 = 0.f, u1 = 0.f, v0 = 0.f, v1 = 0.f;
#pragma unroll
    for (int h = 0; h < HH; h++) {
        int base = h * DD;
        float a0 = fmaf(xv, swq[base + lane], sbq[base + lane]);
        float a1 = fmaf(xv, swq[base + 32 + lane], sbq[base + 32 + lane]);
        float phi0 = (a0 > 0.f) ? (a0 + 1.f) : __expf(a0);
        float phi1 = (a1 > 0.f) ? (a1 + 1.f) : __expf(a1);
        float qv = phi0 * swv[base + lane] + phi1 * swv[base + 32 + lane];
        float qb = phi0 * sbv[base + lane] + phi1 * sbv[base + 32 + lane];
#pragma unroll
        for (int o = 16; o; o >>= 1) {
            qv += __shfl_xor_sync(0xffffffffu, qv, o);
            qb += __shfl_xor_sync(0xffffffffu, qb, o);
        }
        float s1v = ss1[h], s2v = ss2[h];
        float al = qv * s2v + qb * s1v;
        float be = qv * s1v + qb * (float)MMEM;
        u0 += al * suv[base + lane] + be * sub[base + lane];
        u1 += al * suv[base + 32 + lane] + be * sub[base + 32 + lane];
        v0 += al * svv[base + lane] + be * svb[base + lane];
        v1 += al * svv[base + 32 + lane] + be * svb[base + 32 + lane];
    }
    float U0 = u0 + sbu[lane], U1 = u1 + sbu[lane + 32];
    float V0 = v0 + sbv2[lane], V1 = v1 + sbv2[lane + 32];
    size_t row = ((size_t)(b * PP + p)) * RR;
    __nv_bfloat16 h0 = __float2bfloat16(U0);
    __nv_bfloat16 h1 = __float2bfloat16(U1);
    g_Uh[row + lane] = h0;
    g_Uh[row + 32 + lane] = h1;
    g_Ul[row + lane] = __float2bfloat16(U0 - __bfloat162float(h0));
    g_Ul[row + 32 + lane] = __float2bfloat16(U1 - __bfloat162float(h1));
    h0 = __float2bfloat16(V0);
    h1 = __float2bfloat16(V1);
    g_Vh[row + lane] = h0;
    g_Vh[row + 32 + lane] = h1;
    g_Vl[row + lane] = __float2bfloat16(V0 - __bfloat162float(h0));
    g_Vl[row + 32 + lane] = __float2bfloat16(V1 - __bfloat162float(h1));
}

// ---------------------------------------------------------------------------
// Stage 3: mma.sync bf16 GEMM (sm_80+ PTX, runs on tensor pipe as HMMA).
// C[b] = U[b] @ V[b]^T with U = Uh+Ul, V = Vh+Vl (drop Ul*Vl term).
// 128x128 CTA tile, 8 warps (2x4), warp tile 64x32, K=64 resident in smem.
// Smem rows are 128B, XOR-swizzled (chunk ^= row&7) -> conflict-free LDS.
// ---------------------------------------------------------------------------
#define TILE_BYTES 16384
#define GEMM_SMEM (4 * TILE_BYTES)

__device__ __forceinline__ void mma16816(float* c, const uint32_t* a, const uint32_t* b) {
    asm volatile(
        "mma.sync.aligned.m16n8k16.row.col.f32.bf16.bf16.f32 "
        "{%0,%1,%2,%3}, {%4,%5,%6,%7}, {%8,%9}, {%0,%1,%2,%3};"
        : "+f"(c[0]), "+f"(c[1]), "+f"(c[2]), "+f"(c[3])
        : "r"(a[0]), "r"(a[1]), "r"(a[2]), "r"(a[3]), "r"(b[0]), "r"(b[1]));
}

__global__ void __launch_bounds__(256) gemm_kernel(float* __restrict__ C) {
    extern __shared__ char smem[];
    uint32_t* s32 = (uint32_t*)smem;
    int tid = threadIdx.x, wid = tid >> 5, lane = tid & 31;
    int b = blockIdx.z;
    int m0 = blockIdx.y * 128, n0 = blockIdx.x * 128;

    // ---- load 4 tiles (Ah, Al, Bh, Bl): 128 rows x 128B each, swizzled ----
    const uint4* srcs[4] = {
        (const uint4*)(g_Uh + ((size_t)(b * PP + m0)) * RR),
        (const uint4*)(g_Ul + ((size_t)(b * PP + m0)) * RR),
        (const uint4*)(g_Vh + ((size_t)(b * PP + n0)) * RR),
        (const uint4*)(g_Vl + ((size_t)(b * PP + n0)) * RR)};
#pragma unroll
    for (int t = 0; t < 4; t++) {
        uint4* dst = (uint4*)(smem + t * TILE_BYTES);
#pragma unroll
        for (int i = tid; i < 1024; i += 256) {
            int row = i >> 3, c = i & 7;
            dst[row * 8 + (c ^ (row & 7))] = srcs[t][i];
        }
    }
    __syncthreads();

    // word-index bases of each tile
    const int AhW = 0, AlW = TILE_BYTES / 4, BhW = 2 * TILE_BYTES / 4, BlW = 3 * TILE_BYTES / 4;
    int wm = wid >> 2, wn = wid & 3;     // warp grid 2x4
    int grp = lane >> 2, qid = lane & 3;

    float acc[4][4][4];
#pragma unroll
    for (int mi = 0; mi < 4; mi++)
#pragma unroll
        for (int ni = 0; ni < 4; ni++)
#pragma unroll
            for (int j = 0; j < 4; j++) acc[mi][ni][j] = 0.f;

#pragma unroll
    for (int k = 0; k < 4; k++) {
        uint32_t Ahf[4][4], Alf[4][4], Bhf[4][2], Blf[4][2];
#pragma unroll
        for (int mi = 0; mi < 4; mi++) {
            int r0 = wm * 64 + mi * 16 + grp, r1 = r0 + 8;
            int c0 = (2 * k) ^ (r0 & 7), c1 = (2 * k + 1) ^ (r0 & 7);
            Ahf[mi][0] = s32[AhW + r0 * 32 + c0 * 4 + qid];
            Ahf[mi][1] = s32[AhW + r1 * 32 + c0 * 4 + qid];
            Ahf[mi][2] = s32[AhW + r0 * 32 + c1 * 4 + qid];
            Ahf[mi][3] = s32[AhW + r1 * 32 + c1 * 4 + qid];
            Alf[mi][0] = s32[AlW + r0 * 32 + c0 * 4 + qid];
            Alf[mi][1] = s32[AlW + r1 * 32 + c0 * 4 + qid];
            Alf[mi][2] = s32[AlW + r0 * 32 + c1 * 4 + qid];
            Alf[mi][3] = s32[AlW + r1 * 32 + c1 * 4 + qid];
        }
#pragma unroll
        for (int ni = 0; ni < 4; ni++) {
            int rb = wn * 32 + ni * 8 + grp;
            int cb0 = (2 * k) ^ (rb & 7), cb1 = (2 * k + 1) ^ (rb & 7);
            Bhf[ni][0] = s32[BhW + rb * 32 + cb0 * 4 + qid];
            Bhf[ni][1] = s32[BhW + rb * 32 + cb1 * 4 + qid];
            Blf[ni][0] = s32[BlW + rb * 32 + cb0 * 4 + qid];
            Blf[ni][1] = s32[BlW + rb * 32 + cb1 * 4 + qid];
        }
#pragma unroll
        for (int mi = 0; mi < 4; mi++)
#pragma unroll
            for (int ni = 0; ni < 4; ni++) {
                mma16816(acc[mi][ni], Ahf[mi], Bhf[ni]);
                mma16816(acc[mi][ni], Ahf[mi], Blf[ni]);
                mma16816(acc[mi][ni], Alf[mi], Bhf[ni]);
            }
    }

    // ---- epilogue: direct float2 stores (fragment-native layout) ----
    float* Cb = C + ((size_t)b << 20);
#pragma unroll
    for (int mi = 0; mi < 4; mi++) {
        int row = m0 + wm * 64 + mi * 16 + grp;
#pragma unroll
        for (int ni = 0; ni < 4; ni++) {
            int col = n0 + wn * 32 + ni * 8 + qid * 2;
            *(float2*)&Cb[(size_t)row * PP + col] = make_float2(acc[mi][ni][0], acc[mi][ni][1]);
            *(float2*)&Cb[(size_t)(row + 8) * PP + col] = make_float2(acc[mi][ni][2], acc[mi][ni][3]);
        }
    }
}

extern "C" void kernel_launch(void* const* d_in, const int* in_sizes, int n_in,
                              void* d_out, int out_size) {
    const float* x    = (const float*)d_in[0];
    const float* w_q  = (const float*)d_in[1];
    const float* b_q  = (const float*)d_in[2];
    const float* w_k  = (const float*)d_in[3];
    // d_in[4] = b_k: cancels in softmax over p — unused.
    const float* w_v  = (const float*)d_in[5];
    const float* b_v  = (const float*)d_in[6];
    const float* w_mem = (const float*)d_in[7];
    const float* w_u  = (const float*)d_in[8];
    const float* b_u  = (const float*)d_in[9];
    const float* w_v2 = (const float*)d_in[10];
    const float* b_v2 = (const float*)d_in[11];
    float* out = (float*)d_out;

    cudaFuncSetAttribute(gemm_kernel, cudaFuncAttributeMaxDynamicSharedMemorySize, GEMM_SMEM);

    precompute_kernel<<<5, 512>>>(w_k, w_mem, w_u, w_v, b_v, w_v2);
    stage1_kernel<<<BB * HH, 256>>>(x);
    stage2_kernel<<<(BB * PP) / 32, 1024>>>(x, w_q, b_q, w_v, b_v, b_u, b_v2);
    gemm_kernel<<<dim3(PP / 128, PP / 128, BB), 256, GEMM_SMEM>>>(out);
}

// round 4
// speedup vs baseline: 1.9170x; 1.3068x over previous
#include <cuda_runtime.h>
#include <cuda_bf16.h>
#include <cstdint>

#define BB 32
#define PP 1024
#define HH 8
#define DD 64
#define HIDN 512
#define MMEM 64
#define RR 64

// ------------------------- device scratch (no allocs) -----------------------
__device__ float g_A[HH * MMEM];
__device__ float g_s1[BB * HH];
__device__ float g_s2[BB * HH];
__device__ float g_WUv[HH * RR];
__device__ float g_WUb[HH * RR];
__device__ float g_WVv[HH * RR];
__device__ float g_WVb[HH * RR];
// per-batch rank-16 core: G (16x16), cu/av (16), g0
__device__ float g_G[BB * 256];
__device__ float g_cu[BB * 16];
__device__ float g_av[BB * 16];
__device__ float g_g0[BB];
// bf16 split operands, layout [b][p][16] (rows of 16 bf16 = 32B)
__device__ __nv_bfloat16 g_Hh[BB * PP * 16];
__device__ __nv_bfloat16 g_Hl[BB * PP * 16];
__device__ __nv_bfloat16 g_Fh[BB * PP * 16];
__device__ __nv_bfloat16 g_Fl[BB * PP * 16];
__device__ float g_c[BB * PP];
__device__ float g_a[BB * PP];

// ---------------------------------------------------------------------------
// Stage 0: tiny precomputes (b_k cancels in the softmax over p).
// ---------------------------------------------------------------------------
__global__ void precompute_kernel(const float* __restrict__ w_k,
                                  const float* __restrict__ w_mem,
                                  const float* __restrict__ w_u,
                                  const float* __restrict__ w_v,
                                  const float* __restrict__ b_v,
                                  const float* __restrict__ w_v2) {
    int which = blockIdx.x;
    int t = threadIdx.x;  // 0..511
    if (which == 0) {
        int h = t >> 6, m = t & 63;
        float s = 0.f;
#pragma unroll
        for (int d = 0; d < DD; d++) s += w_k[h * DD + d] * w_mem[m * DD + d];
        g_A[h * MMEM + m] = s;
    } else {
        int h = t >> 6, r = t & 63;
        const float* wsrc = (which <= 2) ? w_u : w_v2;
        const float* vec = (which & 1) ? w_v : b_v;
        float s = 0.f;
#pragma unroll
        for (int d = 0; d < DD; d++) s += wsrc[r * HIDN + h * DD + d] * vec[h * DD + d];
        if (which == 1) g_WUv[h * RR + r] = s;
        else if (which == 2) g_WUb[h * RR + r] = s;
        else if (which == 3) g_WVv[h * RR + r] = s;
        else g_WVb[h * RR + r] = s;
    }
}

// ---------------------------------------------------------------------------
// Stage 1: per (b,h): t[m] = softmax-weighted mean of x; s1=sum t, s2=sum t^2
// ---------------------------------------------------------------------------
__global__ void stage1_kernel(const float* __restrict__ x) {
    __shared__ float xs[PP];
    __shared__ float red[16];
    __shared__ float ts[MMEM];
    __shared__ float smm[2];
    int b = blockIdx.x >> 3;
    int h = blockIdx.x & 7;
    int tid = threadIdx.x;  // 256 threads
    float mx = -1e30f, mn = 1e30f;
    for (int i = tid; i < PP; i += 256) {
        float v = x[b * PP + i];
        xs[i] = v;
        mx = fmaxf(mx, v);
        mn = fminf(mn, v);
    }
#pragma unroll
    for (int o = 16; o; o >>= 1) {
        mx = fmaxf(mx, __shfl_xor_sync(0xffffffffu, mx, o));
        mn = fminf(mn, __shfl_xor_sync(0xffffffffu, mn, o));
    }
    int warp = tid >> 5, lane = tid & 31;
    if (lane == 0) { red[warp] = mx; red[8 + warp] = mn; }
    __syncthreads();
    if (tid == 0) {
        float a = red[0], c = red[8];
#pragma unroll
        for (int w = 1; w < 8; w++) { a = fmaxf(a, red[w]); c = fminf(c, red[8 + w]); }
        smm[0] = a; smm[1] = c;
    }
    __syncthreads();
    float bmax = smm[0], bmin = smm[1];
#pragma unroll
    for (int mi = 0; mi < 8; mi++) {
        int m = warp * 8 + mi;
        float a = g_A[h * MMEM + m];
        float shift = (a > 0.f) ? a * bmax : a * bmin;
        float Z = 0.f, Zx = 0.f;
        for (int p = lane; p < PP; p += 32) {
            float xv = xs[p];
            float e = __expf(fmaf(a, xv, -shift));
            Z += e;
            Zx = fmaf(e, xv, Zx);
        }
#pragma unroll
        for (int o = 16; o; o >>= 1) {
            Z += __shfl_xor_sync(0xffffffffu, Z, o);
            Zx += __shfl_xor_sync(0xffffffffu, Zx, o);
        }
        if (lane == 0) ts[m] = Zx / Z;
    }
    __syncthreads();
    if (tid < 32) {
        float t0 = ts[tid], t1 = ts[tid + 32];
        float s1 = t0 + t1, s2 = t0 * t0 + t1 * t1;
#pragma unroll
        for (int o = 16; o; o >>= 1) {
            s1 += __shfl_xor_sync(0xffffffffu, s1, o);
            s2 += __shfl_xor_sync(0xffffffffu, s2, o);
        }
        if (tid == 0) { g_s1[blockIdx.x] = s1; g_s2[blockIdx.x] = s2; }
    }
}

// ---------------------------------------------------------------------------
// Stage 1b: per-batch rank-16 core.
//  Mu[i,r] (i<8):  s2_i*WUv[i,r] + s1_i*WUb[i,r]
//  Mu[8+i,r]:      s1_i*WUv[i,r] + 64*WUb[i,r]     (Mv analogous with WV*)
//  G = Mu Mv^T, cu = Mu b_v2, av = Mv b_u, g0 = b_u . b_v2
// ---------------------------------------------------------------------------
__global__ void prep_kernel(const float* __restrict__ b_u,
                            const float* __restrict__ b_v2) {
    __shared__ float Mu[16][64], Mv[16][64];
    int b = blockIdx.x;
    int t = threadIdx.x;  // 256
#pragma unroll
    for (int idx = t; idx < 1024; idx += 256) {
        int i = idx >> 6, r = idx & 63;
        int h = i & 7;
        float s1 = g_s1[b * HH + h], s2 = g_s2[b * HH + h];
        float uv = g_WUv[h * RR + r], ub = g_WUb[h * RR + r];
        float vv = g_WVv[h * RR + r], vb = g_WVb[h * RR + r];
        if (i < 8) {
            Mu[i][r] = s2 * uv + s1 * ub;
            Mv[i][r] = s2 * vv + s1 * vb;
        } else {
            Mu[i][r] = s1 * uv + 64.f * ub;
            Mv[i][r] = s1 * vv + 64.f * vb;
        }
    }
    __syncthreads();
    {
        int i = t >> 4, j = t & 15;
        float s = 0.f;
#pragma unroll
        for (int r = 0; r < 64; r++) s += Mu[i][r] * Mv[j][r];
        g_G[b * 256 + i * 16 + j] = s;
    }
    if (t < 16) {
        float s = 0.f;
#pragma unroll
        for (int r = 0; r < 64; r++) s += Mu[t][r] * b_v2[r];
        g_cu[b * 16 + t] = s;
    } else if (t < 32) {
        float s = 0.f;
#pragma unroll
        for (int r = 0; r < 64; r++) s += Mv[t - 16][r] * b_u[r];
        g_av[b * 16 + t - 16] = s;
    } else if (t == 32) {
        float s = 0.f;
#pragma unroll
        for (int r = 0; r < 64; r++) s += b_u[r] * b_v2[r];
        g_g0[b] = s;
    }
}

// ---------------------------------------------------------------------------
// Stage 2: one warp per (b,p). Compute features F (qv_h, qb_h), then
// H = F G, c = F.cu + g0, a = F.av. Write bf16 hi/lo splits of H and F.
// ---------------------------------------------------------------------------
__global__ void __launch_bounds__(1024) stage2_kernel(const float* __restrict__ x,
                                                      const float* __restrict__ w_q,
                                                      const float* __restrict__ b_q,
                                                      const float* __restrict__ w_v,
                                                      const float* __restrict__ b_v) {
    __shared__ float swq[HIDN], sbq[HIDN], swv[HIDN], sbv[HIDN];
    __shared__ float sG[256], scu[16], sav[16], sg0;
    int tid = threadIdx.x;
    int warp = tid >> 5, lane = tid & 31;
    int g = blockIdx.x * 32 + warp;
    int b = g >> 10;
    int p = g & 1023;
    if (tid < HIDN) {
        swq[tid] = w_q[tid]; sbq[tid] = b_q[tid];
        swv[tid] = w_v[tid]; sbv[tid] = b_v[tid];
        if (tid < 256) sG[tid] = g_G[b * 256 + tid];
        if (tid < 16) { scu[tid] = g_cu[b * 16 + tid]; sav[tid] = g_av[b * 16 + tid]; }
        if (tid == 0) sg0 = g_g0[b];
    }
    __syncthreads();
    float xv = x[b * PP + p];
    int jl = lane & 15;  // duplicated across half-warps
    float Hacc = 0.f, Floc = 0.f;
#pragma unroll
    for (int h = 0; h < HH; h++) {
        int base = h * DD;
        float a0 = fmaf(xv, swq[base + lane], sbq[base + lane]);
        float a1 = fmaf(xv, swq[base + 32 + lane], sbq[base + 32 + lane]);
        float phi0 = (a0 > 0.f) ? (a0 + 1.f) : __expf(a0);
        float phi1 = (a1 > 0.f) ? (a1 + 1.f) : __expf(a1);
        float qv = phi0 * swv[base + lane] + phi1 * swv[base + 32 + lane];
        float qb = phi0 * sbv[base + lane] + phi1 * sbv[base + 32 + lane];
#pragma unroll
        for (int o = 16; o; o >>= 1) {
            qv += __shfl_xor_sync(0xffffffffu, qv, o);
            qb += __shfl_xor_sync(0xffffffffu, qb, o);
        }
        Hacc = fmaf(qv, sG[h * 16 + jl], Hacc);
        Hacc = fmaf(qb, sG[(8 + h) * 16 + jl], Hacc);
        if (jl == h) Floc = qv;
        if (jl == h + 8) Floc = qb;
    }
    // c and a dots (reduce over 16 feature lanes; lanes 16-31 duplicate)
    float cpart = Floc * scu[jl];
    float apart = Floc * sav[jl];
#pragma unroll
    for (int o = 8; o; o >>= 1) {
        cpart += __shfl_xor_sync(0xffffffffu, cpart, o);
        apart += __shfl_xor_sync(0xffffffffu, apart, o);
    }
    size_t row = ((size_t)(b * PP + p)) * 16;
    if (lane < 16) {
        __nv_bfloat16 hh = __float2bfloat16(Hacc);
        g_Hh[row + jl] = hh;
        g_Hl[row + jl] = __float2bfloat16(Hacc - __bfloat162float(hh));
        if (lane == 0) g_c[b * PP + p] = cpart + sg0;
    } else {
        __nv_bfloat16 fh = __float2bfloat16(Floc);
        g_Fh[row + jl] = fh;
        g_Fl[row + jl] = __float2bfloat16(Floc - __bfloat162float(fh));
        if (lane == 16) g_a[b * PP + p] = apart;
    }
}

// ---------------------------------------------------------------------------
// Stage 3: K=16 bf16-split GEMM + rank-1 fp32 correction.
// C[b][p][q] = H[p].F[q] (Karatsuba: HhFh + HhFl + HlFh) + c[p] + a[q].
// 128x128 CTA tile, 8 warps (2x4), warp 64x32, no smem: fragments straight
// from gmem (tiny L2-resident operands).
// ---------------------------------------------------------------------------
__device__ __forceinline__ void mma16816(float* c, const uint32_t* a, const uint32_t* b) {
    asm volatile(
        "mma.sync.aligned.m16n8k16.row.col.f32.bf16.bf16.f32 "
        "{%0,%1,%2,%3}, {%4,%5,%6,%7}, {%8,%9}, {%0,%1,%2,%3};"
        : "+f"(c[0]), "+f"(c[1]), "+f"(c[2]), "+f"(c[3])
        : "r"(a[0]), "r"(a[1]), "r"(a[2]), "r"(a[3]), "r"(b[0]), "r"(b[1]));
}

__global__ void __launch_bounds__(256, 2) gemm_kernel(float* __restrict__ C) {
    int tid = threadIdx.x, wid = tid >> 5, lane = tid & 31;
    int b = blockIdx.z;
    int m0 = blockIdx.y * 128, n0 = blockIdx.x * 128;
    int wm = wid >> 2, wn = wid & 3;
    int grp = lane >> 2, qid = lane & 3;

    int mbase = b * PP + m0 + wm * 64;           // H rows for this warp
    int nbase = b * PP + n0 + wn * 32;           // F rows for this warp
    const uint32_t* Hh = (const uint32_t*)g_Hh + (size_t)mbase * 8;
    const uint32_t* Hl = (const uint32_t*)g_Hl + (size_t)mbase * 8;
    const uint32_t* Fh = (const uint32_t*)g_Fh + (size_t)nbase * 8;
    const uint32_t* Fl = (const uint32_t*)g_Fl + (size_t)nbase * 8;

    // B fragments: 4 n-subtiles x {hi,lo} x 2 regs
    uint32_t Bh[4][2], Bl[4][2];
#pragma unroll
    for (int ni = 0; ni < 4; ni++) {
        int r = ni * 8 + grp;
        Bh[ni][0] = Fh[r * 8 + qid];
        Bh[ni][1] = Fh[r * 8 + 4 + qid];
        Bl[ni][0] = Fl[r * 8 + qid];
        Bl[ni][1] = Fl[r * 8 + 4 + qid];
    }

    float acc[4][4][4];
#pragma unroll
    for (int mi = 0; mi < 4; mi++) {
        int r0 = mi * 16 + grp, r1 = r0 + 8;
        uint32_t Ah[4], Al[4];
        Ah[0] = Hh[r0 * 8 + qid];     Ah[1] = Hh[r1 * 8 + qid];
        Ah[2] = Hh[r0 * 8 + 4 + qid]; Ah[3] = Hh[r1 * 8 + 4 + qid];
        Al[0] = Hl[r0 * 8 + qid];     Al[1] = Hl[r1 * 8 + qid];
        Al[2] = Hl[r0 * 8 + 4 + qid]; Al[3] = Hl[r1 * 8 + 4 + qid];
#pragma unroll
        for (int ni = 0; ni < 4; ni++) {
#pragma unroll
            for (int j = 0; j < 4; j++) acc[mi][ni][j] = 0.f;
            mma16816(acc[mi][ni], Ah, Bh[ni]);
            mma16816(acc[mi][ni], Ah, Bl[ni]);
            mma16816(acc[mi][ni], Al, Bh[ni]);
        }
    }

    // rank-1 correction + store
    float* Cb = C + ((size_t)b << 20);
    const float* cp = g_c + mbase;
    const float* ap = g_a + nbase;
#pragma unroll
    for (int mi = 0; mi < 4; mi++) {
        int r0 = mi * 16 + grp;
        float c0 = cp[r0], c1 = cp[r0 + 8];
        int row = m0 + wm * 64 + r0;
#pragma unroll
        for (int ni = 0; ni < 4; ni++) {
            int cq = ni * 8 + qid * 2;
            float a0 = ap[cq], a1 = ap[cq + 1];
            int col = n0 + wn * 32 + cq;
            *(float2*)&Cb[(size_t)row * PP + col] =
                make_float2(acc[mi][ni][0] + c0 + a0, acc[mi][ni][1] + c0 + a1);
            *(float2*)&Cb[(size_t)(row + 8) * PP + col] =
                make_float2(acc[mi][ni][2] + c1 + a0, acc[mi][ni][3] + c1 + a1);
        }
    }
}

extern "C" void kernel_launch(void* const* d_in, const int* in_sizes, int n_in,
                              void* d_out, int out_size) {
    const float* x    = (const float*)d_in[0];
    const float* w_q  = (const float*)d_in[1];
    const float* b_q  = (const float*)d_in[2];
    const float* w_k  = (const float*)d_in[3];
    // d_in[4] = b_k: cancels in softmax over p — unused.
    const float* w_v  = (const float*)d_in[5];
    const float* b_v  = (const float*)d_in[6];
    const float* w_mem = (const float*)d_in[7];
    const float* w_u  = (const float*)d_in[8];
    const float* b_u  = (const float*)d_in[9];
    const float* w_v2 = (const float*)d_in[10];
    const float* b_v2 = (const float*)d_in[11];
    float* out = (float*)d_out;

    precompute_kernel<<<5, 512>>>(w_k, w_mem, w_u, w_v, b_v, w_v2);
    stage1_kernel<<<BB * HH, 256>>>(x);
    prep_kernel<<<BB, 256>>>(b_u, b_v2);
    stage2_kernel<<<(BB * PP) / 32, 1024>>>(x, w_q, b_q, w_v, b_v);
    gemm_kernel<<<dim3(PP / 128, PP / 128, BB), 256>>>(out);
}